// round 15
// baseline (speedup 1.0000x reference)
#include <cuda_runtime.h>
#include <math.h>

#define BB 4
#define CC 256
#define HH 56
#define WW 56
#define NPIX 3136
#define TT 16
#define MCH 64
#define DD 128
#define KH 28
#define KW 28
#define KK 784
#define TOPK 32
#define GTAB_N 6051
#define TS 128
#define NB 25      /* ceil(3136/128) */
#define NTRI 325   /* 25*26/2 */

// ---------------- scratch (device globals; no allocation) ----------------
__device__ float d_fmp[BB * NPIX * MCH];              // [b][n][m]
__device__ float d_rp[TT * BB * HH * KW * MCH];       // [t][b][y][kx][m]
__device__ float d_Z[BB * TT * KK * DD];              // [b][t][k][d]
__device__ float d_gemb[BB * KK * DD];                // [b][k][d]
__device__ __align__(128) float d_Saff[(size_t)BB * NPIX * NPIX];
__device__ float d_topv[BB * NPIX * TOPK];
__device__ int   d_topi[BB * NPIX * TOPK];
__device__ float d_irow[BB * NPIX];
__device__ float d_cols[BB * NPIX];                   // colsum, then inverted
__device__ float d_Gtab[GTAB_N];

// ---------------- f32x2 packed helpers (bit-exact dual IEEE-RN FMA) ------
__device__ __forceinline__ unsigned long long pk2(float lo, float hi) {
    unsigned long long r;
    asm("mov.b64 %0, {%1, %2};" : "=l"(r) : "f"(lo), "f"(hi));
    return r;
}
__device__ __forceinline__ void upk2(unsigned long long v, float &lo, float &hi) {
    asm("mov.b64 {%0, %1}, %2;" : "=f"(lo), "=f"(hi) : "l"(v));
}
__device__ __forceinline__ void ffma2(unsigned long long &d,
                                      unsigned long long a, unsigned long long b) {
    asm("fma.rn.f32x2 %0, %1, %2, %0;" : "+l"(d) : "l"(a), "l"(b));
}

// ---------------- init: G table + colsum reset (every replay) ------------
__global__ void k_init() {
    int i = blockIdx.x * blockDim.x + threadIdx.x;
    if (i < GTAB_N) d_Gtab[i] = 1.f - expf(-(float)i / 18.f);
    if (i < BB * NPIX) d_cols[i] = (float)NPIX;
}

// ---------------- K1: fmp[b][n][m] = sum_c fm[b][c][n] * pw_w[m][c] ------
__global__ void k_fmp(const float* __restrict__ fm, const float* __restrict__ pw) {
    __shared__ float sF[32][32];
    __shared__ float sW[32][64];
    int b = blockIdx.y;
    int n0 = blockIdx.x * 32;
    int t = threadIdx.x;
    int nl = t & 31;
    int m0 = (t >> 5) * 8;
    float acc[8];
#pragma unroll
    for (int j = 0; j < 8; j++) acc[j] = 0.f;
    for (int c0 = 0; c0 < CC; c0 += 32) {
        __syncthreads();
#pragma unroll
        for (int q = 0; q < 4; q++) {
            int l = t + q * 256; int c = l >> 5; int n = l & 31;
            sF[c][n] = fm[(b * CC + c0 + c) * NPIX + n0 + n];
        }
#pragma unroll
        for (int q = 0; q < 8; q++) {
            int l = t + q * 256; int c = l >> 6; int m = l & 63;
            sW[c][m] = pw[m * CC + c0 + c];
        }
        __syncthreads();
#pragma unroll
        for (int c = 0; c < 32; c++) {
            float a = sF[c][nl];
#pragma unroll
            for (int j = 0; j < 8; j++) acc[j] += a * sW[c][m0 + j];
        }
    }
#pragma unroll
    for (int j = 0; j < 8; j++)
        d_fmp[(size_t)(b * NPIX + n0 + nl) * MCH + m0 + j] = acc[j];
}

// --- K2: fused affine-warp bilinear sample + 9-wide row pooling ----------
__global__ void __launch_bounds__(256) k_warppool(const float* __restrict__ A) {
    __shared__ float2 sw[WW * 32];        // 56 x 32 float2 = 14336 B
    int bid = blockIdx.x;                 // tb*HH + y
    int y = bid % HH;
    int tb = bid / HH;                    // tt*4 + b
    int b = tb & 3;
    int tt = tb >> 2;
    int t = threadIdx.x;
    int w = t >> 5, lane = t & 31;
    const float* Ar = A + tt * 6;
    float gy = (2.f * (float)y + 1.f) / (float)HH - 1.f;
    const float2* p = (const float2*)(d_fmp + (size_t)b * NPIX * MCH);

    for (int x = w; x < WW; x += 8) {
        float gx = (2.f * (float)x + 1.f) / (float)WW - 1.f;
        float grx = gx * Ar[0] + gy * Ar[1] + Ar[2];
        float gry = gx * Ar[3] + gy * Ar[4] + Ar[5];
        float ix = ((grx + 1.f) * (float)WW - 1.f) * 0.5f;
        float iy = ((gry + 1.f) * (float)HH - 1.f) * 0.5f;
        float x0f = floorf(ix), y0f = floorf(iy);
        float wx = ix - x0f, wy = iy - y0f;
        int x0 = (int)x0f, y0 = (int)y0f;
        int x0c = min(max(x0, 0), WW - 1), x1c = min(max(x0 + 1, 0), WW - 1);
        int y0c = min(max(y0, 0), HH - 1), y1c = min(max(y0 + 1, 0), HH - 1);
        float2 v00 = p[(y0c * WW + x0c) * 32 + lane];
        float2 v01 = p[(y0c * WW + x1c) * 32 + lane];
        float2 v10 = p[(y1c * WW + x0c) * 32 + lane];
        float2 v11 = p[(y1c * WW + x1c) * 32 + lane];
        float w00 = (1.f - wx) * (1.f - wy), w01 = wx * (1.f - wy);
        float w10 = (1.f - wx) * wy,         w11 = wx * wy;
        float2 o;
        o.x = v00.x * w00 + v01.x * w01 + v10.x * w10 + v11.x * w11;
        o.y = v00.y * w00 + v01.y * w01 + v10.y * w10 + v11.y * w11;
        sw[x * 32 + lane] = o;
    }
    __syncthreads();

    for (int kx = w; kx < KW; kx += 8) {
        float2 acc = make_float2(0.f, 0.f);
        int xs0 = 2 * kx - 4;
#pragma unroll
        for (int d = 0; d < 9; d++) {
            int xx = xs0 + d;
            if (xx >= 0 && xx < WW) {
                float2 v = sw[xx * 32 + lane];
                acc.x += v.x; acc.y += v.y;
            }
        }
        ((float2*)d_rp)[((size_t)(tb * HH + y) * KW + kx) * 32 + lane] = acc;
    }
}

// ------- K2c: col pool + /81 + pw_b + proj (64->128) + L2 normalize ------
// Two units of 64 threads per block (one ky each); each thread computes TWO
// d-columns (d, d+64). All accumulation chains / rounding identical to the
// validated path -> bit-exact Z.
#define ZP_SMEM ((DD * 65 + 2 * MCH * 36 + 2 * 4 * KW) * 4)
__global__ void __launch_bounds__(128) k_zproj(const float* __restrict__ pwb,
                                               const float* __restrict__ prw,
                                               const float* __restrict__ prb) {
    extern __shared__ float zsm[];
    float* w_s  = zsm;                         // [d][m] pad 65
    float* xs_a = zsm + DD * 65;               // 2 units x [m][kx] pad 36
    float* reda = xs_a + 2 * MCH * 36;         // 2 units x 4*KW
    int bid = blockIdx.x;                      // tb*14 + kyp
    int kyp = bid % (KH / 2);
    int tb = bid / (KH / 2);                   // tt*4 + b
    int b = tb & 3, tt = tb >> 2;
    int t = threadIdx.x;
    int u = t >> 6;                            // unit 0/1
    int ut = t & 63;                           // d0 = ut, d1 = ut+64
    int ky = 2 * kyp + u;
    float* xs_u = xs_a + u * (MCH * 36);
    float* red_u = reda + u * (4 * KW);

    {
        const float4* p4 = (const float4*)prw;    // 2048 float4
#pragma unroll
        for (int i = 0; i < 16; i++) {
            int idx4 = t + i * 128;
            float4 v = p4[idx4];
            int idx = idx4 * 4;
            int d = idx >> 6, m = idx & 63;
            float* w = &w_s[d * 65 + m];
            w[0] = v.x; w[1] = v.y; w[2] = v.z; w[3] = v.w;
        }
    }

    {
        float a[28];
#pragma unroll
        for (int i = 0; i < 28; i++) a[i] = 0.f;
        int ys0 = 2 * ky - 4;
        const float* rbase = d_rp + (size_t)tb * HH * KW * MCH;
        for (int dyy = 0; dyy < 9; dyy++) {
            int yy = ys0 + dyy;
            if (yy < 0 || yy >= HH) continue;
            const float* rrow = rbase + (size_t)yy * (KW * MCH);
#pragma unroll
            for (int i = 0; i < 28; i++) a[i] += rrow[ut + i * 64];
        }
        float pwbm = pwb[ut];
#pragma unroll
        for (int i = 0; i < 28; i++)
            xs_u[ut * 36 + i] = a[i] / 81.f + pwbm;     // exact R3 rounding
    }
    __syncthreads();

    float acc0[28], acc1[28];
    float pb0 = prb[ut], pb1 = prb[ut + 64];
#pragma unroll
    for (int p = 0; p < 28; p++) { acc0[p] = pb0; acc1[p] = pb1; }
    const float* wr0 = w_s + ut * 65;
    const float* wr1 = w_s + (ut + 64) * 65;
    for (int m = 0; m < MCH; m++) {
        float w0 = wr0[m];
        float w1 = wr1[m];
        const float4* xr = (const float4*)(xs_u + m * 36);
#pragma unroll
        for (int q = 0; q < 7; q++) {
            float4 x4 = xr[q];
            acc0[4 * q]     += x4.x * w0;  acc1[4 * q]     += x4.x * w1;
            acc0[4 * q + 1] += x4.y * w0;  acc1[4 * q + 1] += x4.y * w1;
            acc0[4 * q + 2] += x4.z * w0;  acc1[4 * q + 2] += x4.z * w1;
            acc0[4 * q + 3] += x4.w * w0;  acc1[4 * q + 3] += x4.w * w1;
        }
    }

    int lane = t & 31;
    int wu = (t >> 5) & 1;                 // warp within unit
#pragma unroll
    for (int p = 0; p < 28; p++) {
        float sq0 = acc0[p] * acc0[p];
        float sq1 = acc1[p] * acc1[p];
#pragma unroll
        for (int o = 16; o; o >>= 1) {
            sq0 += __shfl_down_sync(0xffffffffu, sq0, o);
            sq1 += __shfl_down_sync(0xffffffffu, sq1, o);
        }
        if (lane == 0) {
            red_u[wu * 28 + p]       = sq0;
            red_u[(2 + wu) * 28 + p] = sq1;
        }
    }
    __syncthreads();
    size_t zbase = (((size_t)b * TT + tt) * KK + (size_t)ky * KW) * DD;
#pragma unroll
    for (int p = 0; p < 28; p++) {
        float nrm = sqrtf(red_u[p] + red_u[28 + p] + red_u[56 + p] + red_u[84 + p]);
        float inv = 1.f / fmaxf(nrm, 1e-6f);            // exact R3 rounding
        d_Z[zbase + (size_t)p * DD + ut]      = acc0[p] * inv;
        d_Z[zbase + (size_t)p * DD + ut + 64] = acc1[p] * inv;
    }
}

// ---------------- K3: softmax over T, g_emb[b][k][d] ---------------------
__global__ void k_gemb(const float* __restrict__ r) {
    int bid = blockIdx.x;
    int b = bid / KK, k = bid % KK;
    int d = threadIdx.x;
    float v[TT];
#pragma unroll
    for (int t = 0; t < TT; t++)
        v[t] = d_Z[(((size_t)b * TT + t) * KK + k) * DD + d];
    float rv = r[d];
    __shared__ float part[4][TT];
    __shared__ float sv[TT];
    int lane = d & 31, wid = d >> 5;
#pragma unroll
    for (int t = 0; t < TT; t++) {
        float p = v[t] * rv;
#pragma unroll
        for (int o = 16; o; o >>= 1) p += __shfl_down_sync(0xffffffffu, p, o);
        if (lane == 0) part[wid][t] = p;
    }
    __syncthreads();
    if (d < TT) sv[d] = part[0][d] + part[1][d] + part[2][d] + part[3][d];
    __syncthreads();
    float mx = -1e30f;
#pragma unroll
    for (int t = 0; t < TT; t++) mx = fmaxf(mx, 10.f * sv[t]);
    float den = 0.f, g = 0.f;
#pragma unroll
    for (int t = 0; t < TT; t++) {
        float wgt = expf(10.f * sv[t] - mx);
        den += wgt;
        g += wgt * v[t];
    }
    d_gemb[((size_t)b * KK + k) * DD + d] = g / den;
}

// ---------------- K4: E = bilinear(g_emb), L2 normalize, -> d_out --------
__global__ void k_E(float* __restrict__ outE) {
    int bid = blockIdx.x;               // b*NPIX + n
    int n = bid % NPIX;
    int b = bid / NPIX;
    int x = n % WW, y = n / WW;
    int x0 = x >> 1, y0 = y >> 1;
    int x1 = min(x0 + 1, KW - 1), y1 = min(y0 + 1, KH - 1);
    float wx = (x & 1) ? 0.5f : 0.f;
    float wy = (y & 1) ? 0.5f : 0.f;
    float w00 = (1.f - wx) * (1.f - wy), w01 = wx * (1.f - wy);
    float w10 = (1.f - wx) * wy,         w11 = wx * wy;
    const float* g = d_gemb + (size_t)b * KK * DD;
    int d = threadIdx.x;
    float e = w00 * g[(y0 * KW + x0) * DD + d] + w01 * g[(y0 * KW + x1) * DD + d]
            + w10 * g[(y1 * KW + x0) * DD + d] + w11 * g[(y1 * KW + x1) * DD + d];
    float sq = e * e;
#pragma unroll
    for (int o = 16; o; o >>= 1) sq += __shfl_down_sync(0xffffffffu, sq, o);
    __shared__ float r4[4];
    __shared__ float nrm;
    int lane = d & 31, wid = d >> 5;
    if (lane == 0) r4[wid] = sq;
    __syncthreads();
    if (d == 0) nrm = sqrtf(r4[0] + r4[1] + r4[2] + r4[3]);
    __syncthreads();
    outE[(size_t)bid * DD + d] = e * (1.f / fmaxf(nrm, 1e-6f));
}

// ---------------- K5a: Saff = (E E^T) .* G  (exact R7/R12 kernel) ---------
#define LDA 132
__global__ void __launch_bounds__(256) k_saff(const float* __restrict__ E) {
    __shared__ __align__(16) float smem[4 * 16 * LDA];
    float* Ts = smem;
    int b = blockIdx.y;
    int bt = blockIdx.x;
    int bi = 0, rem = bt;
    while (rem >= NB - bi) { rem -= NB - bi; bi++; }
    int bj = bi + rem;
    int n0 = bi * TS, m0 = bj * TS;
    const float* Eb = E + (size_t)b * NPIX * DD;
    float* Sb = d_Saff + (size_t)b * NPIX * NPIX;

    int t = threadIdx.x;
    int ty = t >> 4, tx = t & 15;
    int lr = t >> 2;
    int lc = (t & 3) * 4;

    const float* gA0 = Eb + (size_t)min(n0 + lr,      NPIX - 1) * DD + lc;
    const float* gA1 = Eb + (size_t)min(n0 + lr + 64, NPIX - 1) * DD + lc;
    const float* gB0 = Eb + (size_t)min(m0 + lr,      NPIX - 1) * DD + lc;
    const float* gB1 = Eb + (size_t)min(m0 + lr + 64, NPIX - 1) * DD + lc;

    unsigned long long acc2[8][4];
#pragma unroll
    for (int i = 0; i < 8; i++)
#pragma unroll
        for (int q = 0; q < 4; q++) acc2[i][q] = 0ull;

    float4 pa0 = *(const float4*)gA0;
    float4 pa1 = *(const float4*)gA1;
    float4 pb0 = *(const float4*)gB0;
    float4 pb1 = *(const float4*)gB1;

    float* A0 = smem;
    float* B0 = smem + 16 * LDA;
    float* A1 = smem + 32 * LDA;
    float* B1 = smem + 48 * LDA;

    {
        float av0[4] = {pa0.x, pa0.y, pa0.z, pa0.w};
        float av1[4] = {pa1.x, pa1.y, pa1.z, pa1.w};
        float bv0[4] = {pb0.x, pb0.y, pb0.z, pb0.w};
        float bv1[4] = {pb1.x, pb1.y, pb1.z, pb1.w};
#pragma unroll
        for (int q = 0; q < 4; q++) {
            A0[(lc + q) * LDA + lr]      = av0[q];
            A0[(lc + q) * LDA + lr + 64] = av1[q];
            B0[(lc + q) * LDA + lr]      = bv0[q];
            B0[(lc + q) * LDA + lr + 64] = bv1[q];
        }
    }
    __syncthreads();

#pragma unroll 1
    for (int c = 0; c < 8; c++) {
        float* As = (c & 1) ? A1 : A0;
        float* Bs = (c & 1) ? B1 : B0;
        if (c < 7) {
            int off = (c + 1) * 16;
            pa0 = *(const float4*)(gA0 + off);
            pa1 = *(const float4*)(gA1 + off);
            pb0 = *(const float4*)(gB0 + off);
            pb1 = *(const float4*)(gB1 + off);
        }
#pragma unroll
        for (int kk = 0; kk < 16; kk++) {
            const float* Ak = As + kk * LDA;
            const float* Bk = Bs + kk * LDA;
            float a[8], bb[8];
            *(float4*)(a)      = *(const float4*)(Ak + ty * 4);
            *(float4*)(a + 4)  = *(const float4*)(Ak + 64 + ty * 4);
            *(float4*)(bb)     = *(const float4*)(Bk + tx * 4);
            *(float4*)(bb + 4) = *(const float4*)(Bk + 64 + tx * 4);
            unsigned long long bp[4];
#pragma unroll
            for (int q = 0; q < 4; q++) bp[q] = pk2(bb[2 * q], bb[2 * q + 1]);
#pragma unroll
            for (int i = 0; i < 8; i++) {
                unsigned long long ad = pk2(a[i], a[i]);
#pragma unroll
                for (int q = 0; q < 4; q++) ffma2(acc2[i][q], ad, bp[q]);
            }
        }
        if (c < 7) {
            float* An = (c & 1) ? A0 : A1;
            float* Bn = (c & 1) ? B0 : B1;
            float av0[4] = {pa0.x, pa0.y, pa0.z, pa0.w};
            float av1[4] = {pa1.x, pa1.y, pa1.z, pa1.w};
            float bv0[4] = {pb0.x, pb0.y, pb0.z, pb0.w};
            float bv1[4] = {pb1.x, pb1.y, pb1.z, pb1.w};
#pragma unroll
            for (int q = 0; q < 4; q++) {
                An[(lc + q) * LDA + lr]      = av0[q];
                An[(lc + q) * LDA + lr + 64] = av1[q];
                Bn[(lc + q) * LDA + lr]      = bv0[q];
                Bn[(lc + q) * LDA + lr + 64] = bv1[q];
            }
            __syncthreads();
        }
    }

    float acc[8][8];
#pragma unroll
    for (int i = 0; i < 8; i++)
#pragma unroll
        for (int q = 0; q < 4; q++) upk2(acc2[i][q], acc[i][2 * q], acc[i][2 * q + 1]);

#pragma unroll
    for (int i = 0; i < 8; i++) {
        int n = n0 + ((i < 4) ? (ty * 4 + i) : (64 + ty * 4 + i - 4));
        if (n >= NPIX) continue;
        int nx = n % WW, ny = n / WW;
#pragma unroll
        for (int h = 0; h < 2; h++) {
            int mb = m0 + h * 64 + tx * 4;
            if (mb >= NPIX) continue;
            float4 o;
            float ov[4];
#pragma unroll
            for (int j = 0; j < 4; j++) {
                int m = mb + j;
                int dx = nx - m % WW;
                int dy = ny - m / WW;
                ov[j] = acc[i][h * 4 + j] * __ldg(&d_Gtab[dx * dx + dy * dy]);
            }
            o.x = ov[0]; o.y = ov[1]; o.z = ov[2]; o.w = ov[3];
            *(float4*)(Sb + (size_t)n * NPIX + mb) = o;
        }
    }

    if (bi != bj) {
#pragma unroll 1
        for (int p = 0; p < 4; p++) {
            __syncthreads();
            int jh = p >> 1;
            int txlo = (p & 1) * 8;
            if (tx >= txlo && tx < txlo + 8) {
#pragma unroll
                for (int i = 0; i < 8; i++) {
                    int nl = (i < 4) ? (ty * 4 + i) : (64 + ty * 4 + i - 4);
#pragma unroll
                    for (int j = 0; j < 4; j++) {
                        int mrow = (tx - txlo) * 4 + j;
                        Ts[mrow * LDA + nl] = acc[i][jh * 4 + j];
                    }
                }
            }
            __syncthreads();
#pragma unroll
            for (int q = 0; q < 4; q++) {
                int fi = t + q * 256;
                int rown = fi >> 5;
                int c4 = (fi & 31) * 4;
                int m = m0 + 32 * p + rown;
                if (m >= NPIX) continue;
                int mx = m % WW, my = m / WW;
                float4 v = *(const float4*)(Ts + rown * LDA + c4);
                int nbase = n0 + c4;
                float vv[4] = {v.x, v.y, v.z, v.w};
                float4 o;
                float ov[4];
#pragma unroll
                for (int j = 0; j < 4; j++) {
                    int n = nbase + j;
                    int dx = mx - n % WW;
                    int dy = my - n / WW;
                    ov[j] = vv[j] * __ldg(&d_Gtab[dx * dx + dy * dy]);
                }
                o.x = ov[0]; o.y = ov[1]; o.z = ov[2]; o.w = ov[3];
                *(float4*)(Sb + (size_t)m * NPIX + nbase) = o;
            }
        }
    }
}

// ---------------- K5b: per-row top-32 via 4-level radix select -----------
// Histogram atomics warp-aggregated (__match_any_sync): identical counts,
// no single-bank ATOMS serialization on concentrated exponent bins.
__global__ void __launch_bounds__(256) k_topk() {
    int row = blockIdx.x;           // b*NPIX + n
    int b = row / NPIX;
    int t = threadIdx.x;
    const float4* src4 = (const float4*)(d_Saff + (size_t)row * NPIX);
    __shared__ unsigned int hist[256];
    __shared__ unsigned int sufx[256];
    __shared__ unsigned int s_prefix;
    __shared__ int s_need, s_bin, s_cnt, s_last;
    __shared__ int   seli[TOPK];
    __shared__ float selv[TOPK];
    __shared__ int   redi[8];

    unsigned key[16];
    int nslot = (t < 16) ? 4 : 3;
#pragma unroll
    for (int q = 0; q < 4; q++) {
        if (q < nslot) {
            float4 v = src4[t + q * 256];
            float vv[4] = {v.x, v.y, v.z, v.w};
#pragma unroll
            for (int j = 0; j < 4; j++) {
                unsigned u = __float_as_uint(vv[j]);
                key[q * 4 + j] = (u & 0x80000000u) ? ~u : (u | 0x80000000u);
            }
        } else {
#pragma unroll
            for (int j = 0; j < 4; j++) key[q * 4 + j] = 0u;
        }
    }
    if (t == 0) { s_prefix = 0u; s_need = TOPK; s_cnt = 0; s_last = -1; }

#pragma unroll 1
    for (int level = 0; level < 4; level++) {
        int shift = 24 - level * 8;
        hist[t] = 0;
        __syncthreads();
        unsigned pref = s_prefix;
        int need0 = s_need;
#pragma unroll
        for (int s = 0; s < 16; s++) {
            bool act = ((s >> 2) < nslot);
            unsigned bin = 0;
            if (act) {
                unsigned u = key[s];
                bin = (u >> shift) & 0xFFu;
                if (level != 0 && (u >> (shift + 8)) != (pref >> (shift + 8)))
                    act = false;
            }
            unsigned amask = __ballot_sync(0xffffffffu, act);
            if (act) {
                unsigned mm = __match_any_sync(amask, bin);
                int leader = __ffs(mm) - 1;
                if ((t & 31) == leader)
                    atomicAdd(&hist[bin], (unsigned)__popc(mm));
            }
        }
        __syncthreads();
        if (t < 32) {
            unsigned v[8], s = 0;
#pragma unroll
            for (int q = 7; q >= 0; q--) { s += hist[t * 8 + q]; v[q] = s; }
            unsigned x = s;
#pragma unroll
            for (int off = 1; off < 32; off <<= 1) {
                unsigned y = __shfl_down_sync(0xffffffffu, x, off);
                if (t + off < 32) x += y;
            }
            unsigned ex = x - s;
#pragma unroll
            for (int q = 0; q < 8; q++) sufx[t * 8 + q] = v[q] + ex;
        }
        __syncthreads();
        {
            unsigned ge = sufx[t];
            unsigned gn = (t == 255) ? 0u : sufx[t + 1];
            if (ge >= (unsigned)need0 && gn < (unsigned)need0) s_bin = t;
        }
        __syncthreads();
        if (t == 0) {
            int bsel = s_bin;
            if (bsel < 255) s_need -= (int)sufx[bsel + 1];
            s_prefix |= ((unsigned)bsel << shift);
        }
        __syncthreads();
    }

    unsigned T = s_prefix;
    int needEq = s_need;

#pragma unroll
    for (int s = 0; s < 16; s++) {
        if ((s >> 2) < nslot && key[s] > T) {
            int p = atomicAdd(&s_cnt, 1);
            seli[p] = (t + (s >> 2) * 256) * 4 + (s & 3);
        }
    }
    __syncthreads();
    int lane = t & 31, wid = t >> 5;
#pragma unroll 1
    for (int r = 0; r < needEq; r++) {
        int last = s_last;
        int li = NPIX;
#pragma unroll
        for (int s = 0; s < 16; s++) {
            if ((s >> 2) < nslot && key[s] == T) {
                int i = (t + (s >> 2) * 256) * 4 + (s & 3);
                if (i > last && i < li) li = i;
            }
        }
#pragma unroll
        for (int o = 16; o; o >>= 1) li = min(li, __shfl_down_sync(0xffffffffu, li, o));
        if (lane == 0) redi[wid] = li;
        __syncthreads();
        if (t == 0) {
            int m = redi[0];
#pragma unroll
            for (int w = 1; w < 8; w++) m = min(m, redi[w]);
            seli[s_cnt] = m;
            s_cnt++;
            s_last = m;
        }
        __syncthreads();
    }

    if (t < TOPK) {
        int m = seli[t];
        float v = d_Saff[(size_t)row * NPIX + m];
        selv[t] = v;
        d_topv[row * TOPK + t] = v;
        d_topi[row * TOPK + t] = m;
        atomicAdd(&d_cols[b * NPIX + m], expf(10.f * v) - 1.f);
    }
    __syncthreads();
    if (t == 0) {
        float rs = (float)(NPIX - TOPK);
        for (int j = 0; j < TOPK; j++) rs += expf(10.f * selv[j]);
        d_irow[row] = 1.f / rs;
    }
}

// ---------------- K5c: invert colsums -----------------------------------
__global__ void k_invcol() {
    int i = blockIdx.x * blockDim.x + threadIdx.x;
    if (i < BB * NPIX) d_cols[i] = 1.f / d_cols[i];
}

// ------- K5d: A0 = rank-1 background + top-k scatter overrides -----------
__global__ void __launch_bounds__(256) k_a0(float* __restrict__ outA) {
    int row = blockIdx.x;           // b*NPIX + n
    int b = row / NPIX;
    int t = threadIdx.x;
    float rn = d_irow[row];
    float4* out4 = (float4*)(outA + (size_t)row * NPIX);
    const float4* ic4 = (const float4*)(d_cols + b * NPIX);
    for (int f = t; f < NPIX / 4; f += 256) {
        float4 c = ic4[f];
        float4 o;
        o.x = rn * c.x; o.y = rn * c.y; o.z = rn * c.z; o.w = rn * c.w;
        out4[f] = o;
    }
    __syncthreads();
    if (t < TOPK) {
        int m = d_topi[row * TOPK + t];
        float v = d_topv[row * TOPK + t];
        float e = expf(10.f * v);
        outA[(size_t)row * NPIX + m] = e * e * rn * (d_cols + b * NPIX)[m];
    }
}

// -------------------------------------------------------------------------
extern "C" void kernel_launch(void* const* d_in, const int* in_sizes, int n_in,
                              void* d_out, int out_size) {
    const float* fm  = (const float*)d_in[0];
    const float* A   = (const float*)d_in[1];
    const float* pww = (const float*)d_in[2];
    const float* pwb = (const float*)d_in[3];
    const float* prw = (const float*)d_in[4];
    const float* prb = (const float*)d_in[5];
    const float* r   = (const float*)d_in[6];

    float* outE = (float*)d_out;                        // (B, N, D)
    float* outA = outE + (size_t)BB * NPIX * DD;        // (B, N, N)

    cudaFuncSetAttribute(k_zproj, cudaFuncAttributeMaxDynamicSharedMemorySize,
                         ZP_SMEM);

    k_init<<<49, 256>>>();
    k_fmp<<<dim3(NPIX / 32, BB), 256>>>(fm, pww);
    k_warppool<<<TT * BB * HH, 256>>>(A);
    k_zproj<<<TT * BB * (KH / 2), 128, ZP_SMEM>>>(pwb, prw, prb);
    k_gemb<<<BB * KK, 128>>>(r);
    k_E<<<BB * NPIX, 128>>>(outE);
    k_saff<<<dim3(NTRI, BB), 256>>>(outE);
    k_topk<<<BB * NPIX, 256>>>();
    k_invcol<<<49, 256>>>();
    k_a0<<<BB * NPIX, 256>>>(outA);
}

// round 16
// speedup vs baseline: 1.1424x; 1.1424x over previous
#include <cuda_runtime.h>
#include <math.h>

#define BB 4
#define CC 256
#define HH 56
#define WW 56
#define NPIX 3136
#define TT 16
#define MCH 64
#define DD 128
#define KH 28
#define KW 28
#define KK 784
#define TOPK 32
#define GTAB_N 6051
#define TS 128
#define NB 25      /* ceil(3136/128) */
#define NTRI 325   /* 25*26/2 */

// ---------------- scratch (device globals; no allocation) ----------------
__device__ float d_fmp[BB * NPIX * MCH];              // [b][n][m]
__device__ float d_rp[TT * BB * HH * KW * MCH];       // [t][b][y][kx][m]
__device__ float d_Z[BB * TT * KK * DD];              // [b][t][k][d]
__device__ float d_gemb[BB * KK * DD];                // [b][k][d]
__device__ __align__(128) float d_Saff[(size_t)BB * NPIX * NPIX];
__device__ float d_topv[BB * NPIX * TOPK];
__device__ int   d_topi[BB * NPIX * TOPK];
__device__ float d_irow[BB * NPIX];
__device__ float d_cols[BB * NPIX];                   // colsum, then inverted
__device__ float d_Gtab[GTAB_N];

// ---------------- f32x2 packed helpers (bit-exact dual IEEE-RN FMA) ------
__device__ __forceinline__ unsigned long long pk2(float lo, float hi) {
    unsigned long long r;
    asm("mov.b64 %0, {%1, %2};" : "=l"(r) : "f"(lo), "f"(hi));
    return r;
}
__device__ __forceinline__ void upk2(unsigned long long v, float &lo, float &hi) {
    asm("mov.b64 {%0, %1}, %2;" : "=f"(lo), "=f"(hi) : "l"(v));
}
__device__ __forceinline__ void ffma2(unsigned long long &d,
                                      unsigned long long a, unsigned long long b) {
    asm("fma.rn.f32x2 %0, %1, %2, %0;" : "+l"(d) : "l"(a), "l"(b));
}

// ---------------- init: G table + colsum reset (every replay) ------------
__global__ void k_init() {
    int i = blockIdx.x * blockDim.x + threadIdx.x;
    if (i < GTAB_N) d_Gtab[i] = 1.f - expf(-(float)i / 18.f);
    if (i < BB * NPIX) d_cols[i] = (float)NPIX;
}

// ---------------- K1: fmp[b][n][m] = sum_c fm[b][c][n] * pw_w[m][c] ------
__global__ void k_fmp(const float* __restrict__ fm, const float* __restrict__ pw) {
    __shared__ float sF[32][32];
    __shared__ float sW[32][64];
    int b = blockIdx.y;
    int n0 = blockIdx.x * 32;
    int t = threadIdx.x;
    int nl = t & 31;
    int m0 = (t >> 5) * 8;
    float acc[8];
#pragma unroll
    for (int j = 0; j < 8; j++) acc[j] = 0.f;
    for (int c0 = 0; c0 < CC; c0 += 32) {
        __syncthreads();
#pragma unroll
        for (int q = 0; q < 4; q++) {
            int l = t + q * 256; int c = l >> 5; int n = l & 31;
            sF[c][n] = fm[(b * CC + c0 + c) * NPIX + n0 + n];
        }
#pragma unroll
        for (int q = 0; q < 8; q++) {
            int l = t + q * 256; int c = l >> 6; int m = l & 63;
            sW[c][m] = pw[m * CC + c0 + c];
        }
        __syncthreads();
#pragma unroll
        for (int c = 0; c < 32; c++) {
            float a = sF[c][nl];
#pragma unroll
            for (int j = 0; j < 8; j++) acc[j] += a * sW[c][m0 + j];
        }
    }
#pragma unroll
    for (int j = 0; j < 8; j++)
        d_fmp[(size_t)(b * NPIX + n0 + nl) * MCH + m0 + j] = acc[j];
}

// --- K2: fused affine-warp bilinear sample + 9-wide row pooling ----------
__global__ void __launch_bounds__(256) k_warppool(const float* __restrict__ A) {
    __shared__ float2 sw[WW * 32];        // 56 x 32 float2 = 14336 B
    int bid = blockIdx.x;                 // tb*HH + y
    int y = bid % HH;
    int tb = bid / HH;                    // tt*4 + b
    int b = tb & 3;
    int tt = tb >> 2;
    int t = threadIdx.x;
    int w = t >> 5, lane = t & 31;
    const float* Ar = A + tt * 6;
    float gy = (2.f * (float)y + 1.f) / (float)HH - 1.f;
    const float2* p = (const float2*)(d_fmp + (size_t)b * NPIX * MCH);

    for (int x = w; x < WW; x += 8) {
        float gx = (2.f * (float)x + 1.f) / (float)WW - 1.f;
        float grx = gx * Ar[0] + gy * Ar[1] + Ar[2];
        float gry = gx * Ar[3] + gy * Ar[4] + Ar[5];
        float ix = ((grx + 1.f) * (float)WW - 1.f) * 0.5f;
        float iy = ((gry + 1.f) * (float)HH - 1.f) * 0.5f;
        float x0f = floorf(ix), y0f = floorf(iy);
        float wx = ix - x0f, wy = iy - y0f;
        int x0 = (int)x0f, y0 = (int)y0f;
        int x0c = min(max(x0, 0), WW - 1), x1c = min(max(x0 + 1, 0), WW - 1);
        int y0c = min(max(y0, 0), HH - 1), y1c = min(max(y0 + 1, 0), HH - 1);
        float2 v00 = p[(y0c * WW + x0c) * 32 + lane];
        float2 v01 = p[(y0c * WW + x1c) * 32 + lane];
        float2 v10 = p[(y1c * WW + x0c) * 32 + lane];
        float2 v11 = p[(y1c * WW + x1c) * 32 + lane];
        float w00 = (1.f - wx) * (1.f - wy), w01 = wx * (1.f - wy);
        float w10 = (1.f - wx) * wy,         w11 = wx * wy;
        float2 o;
        o.x = v00.x * w00 + v01.x * w01 + v10.x * w10 + v11.x * w11;
        o.y = v00.y * w00 + v01.y * w01 + v10.y * w10 + v11.y * w11;
        sw[x * 32 + lane] = o;
    }
    __syncthreads();

    for (int kx = w; kx < KW; kx += 8) {
        float2 acc = make_float2(0.f, 0.f);
        int xs0 = 2 * kx - 4;
#pragma unroll
        for (int d = 0; d < 9; d++) {
            int xx = xs0 + d;
            if (xx >= 0 && xx < WW) {
                float2 v = sw[xx * 32 + lane];
                acc.x += v.x; acc.y += v.y;
            }
        }
        ((float2*)d_rp)[((size_t)(tb * HH + y) * KW + kx) * 32 + lane] = acc;
    }
}

// ------- K2c: col pool + /81 + pw_b + proj (64->128) + L2 normalize ------
// Two units of 64 threads per block (one ky each); each thread computes TWO
// d-columns (d, d+64). All accumulation chains / rounding identical to the
// validated path -> bit-exact Z.
#define ZP_SMEM ((DD * 65 + 2 * MCH * 36 + 2 * 4 * KW) * 4)
__global__ void __launch_bounds__(128) k_zproj(const float* __restrict__ pwb,
                                               const float* __restrict__ prw,
                                               const float* __restrict__ prb) {
    extern __shared__ float zsm[];
    float* w_s  = zsm;                         // [d][m] pad 65
    float* xs_a = zsm + DD * 65;               // 2 units x [m][kx] pad 36
    float* reda = xs_a + 2 * MCH * 36;         // 2 units x 4*KW
    int bid = blockIdx.x;                      // tb*14 + kyp
    int kyp = bid % (KH / 2);
    int tb = bid / (KH / 2);                   // tt*4 + b
    int b = tb & 3, tt = tb >> 2;
    int t = threadIdx.x;
    int u = t >> 6;                            // unit 0/1
    int ut = t & 63;                           // d0 = ut, d1 = ut+64
    int ky = 2 * kyp + u;
    float* xs_u = xs_a + u * (MCH * 36);
    float* red_u = reda + u * (4 * KW);

    {
        const float4* p4 = (const float4*)prw;    // 2048 float4
#pragma unroll
        for (int i = 0; i < 16; i++) {
            int idx4 = t + i * 128;
            float4 v = p4[idx4];
            int idx = idx4 * 4;
            int d = idx >> 6, m = idx & 63;
            float* w = &w_s[d * 65 + m];
            w[0] = v.x; w[1] = v.y; w[2] = v.z; w[3] = v.w;
        }
    }

    {
        float a[28];
#pragma unroll
        for (int i = 0; i < 28; i++) a[i] = 0.f;
        int ys0 = 2 * ky - 4;
        const float* rbase = d_rp + (size_t)tb * HH * KW * MCH;
        for (int dyy = 0; dyy < 9; dyy++) {
            int yy = ys0 + dyy;
            if (yy < 0 || yy >= HH) continue;
            const float* rrow = rbase + (size_t)yy * (KW * MCH);
#pragma unroll
            for (int i = 0; i < 28; i++) a[i] += rrow[ut + i * 64];
        }
        float pwbm = pwb[ut];
#pragma unroll
        for (int i = 0; i < 28; i++)
            xs_u[ut * 36 + i] = a[i] / 81.f + pwbm;     // exact R3 rounding
    }
    __syncthreads();

    float acc0[28], acc1[28];
    float pb0 = prb[ut], pb1 = prb[ut + 64];
#pragma unroll
    for (int p = 0; p < 28; p++) { acc0[p] = pb0; acc1[p] = pb1; }
    const float* wr0 = w_s + ut * 65;
    const float* wr1 = w_s + (ut + 64) * 65;
    for (int m = 0; m < MCH; m++) {
        float w0 = wr0[m];
        float w1 = wr1[m];
        const float4* xr = (const float4*)(xs_u + m * 36);
#pragma unroll
        for (int q = 0; q < 7; q++) {
            float4 x4 = xr[q];
            acc0[4 * q]     += x4.x * w0;  acc1[4 * q]     += x4.x * w1;
            acc0[4 * q + 1] += x4.y * w0;  acc1[4 * q + 1] += x4.y * w1;
            acc0[4 * q + 2] += x4.z * w0;  acc1[4 * q + 2] += x4.z * w1;
            acc0[4 * q + 3] += x4.w * w0;  acc1[4 * q + 3] += x4.w * w1;
        }
    }

    int lane = t & 31;
    int wu = (t >> 5) & 1;                 // warp within unit
#pragma unroll
    for (int p = 0; p < 28; p++) {
        float sq0 = acc0[p] * acc0[p];
        float sq1 = acc1[p] * acc1[p];
#pragma unroll
        for (int o = 16; o; o >>= 1) {
            sq0 += __shfl_down_sync(0xffffffffu, sq0, o);
            sq1 += __shfl_down_sync(0xffffffffu, sq1, o);
        }
        if (lane == 0) {
            red_u[wu * 28 + p]       = sq0;
            red_u[(2 + wu) * 28 + p] = sq1;
        }
    }
    __syncthreads();
    size_t zbase = (((size_t)b * TT + tt) * KK + (size_t)ky * KW) * DD;
#pragma unroll
    for (int p = 0; p < 28; p++) {
        float nrm = sqrtf(red_u[p] + red_u[28 + p] + red_u[56 + p] + red_u[84 + p]);
        float inv = 1.f / fmaxf(nrm, 1e-6f);            // exact R3 rounding
        d_Z[zbase + (size_t)p * DD + ut]      = acc0[p] * inv;
        d_Z[zbase + (size_t)p * DD + ut + 64] = acc1[p] * inv;
    }
}

// ---------------- K3: softmax over T, g_emb[b][k][d] ---------------------
__global__ void k_gemb(const float* __restrict__ r) {
    int bid = blockIdx.x;
    int b = bid / KK, k = bid % KK;
    int d = threadIdx.x;
    float v[TT];
#pragma unroll
    for (int t = 0; t < TT; t++)
        v[t] = d_Z[(((size_t)b * TT + t) * KK + k) * DD + d];
    float rv = r[d];
    __shared__ float part[4][TT];
    __shared__ float sv[TT];
    int lane = d & 31, wid = d >> 5;
#pragma unroll
    for (int t = 0; t < TT; t++) {
        float p = v[t] * rv;
#pragma unroll
        for (int o = 16; o; o >>= 1) p += __shfl_down_sync(0xffffffffu, p, o);
        if (lane == 0) part[wid][t] = p;
    }
    __syncthreads();
    if (d < TT) sv[d] = part[0][d] + part[1][d] + part[2][d] + part[3][d];
    __syncthreads();
    float mx = -1e30f;
#pragma unroll
    for (int t = 0; t < TT; t++) mx = fmaxf(mx, 10.f * sv[t]);
    float den = 0.f, g = 0.f;
#pragma unroll
    for (int t = 0; t < TT; t++) {
        float wgt = expf(10.f * sv[t] - mx);
        den += wgt;
        g += wgt * v[t];
    }
    d_gemb[((size_t)b * KK + k) * DD + d] = g / den;
}

// ---------------- K4: E = bilinear(g_emb), L2 normalize, -> d_out --------
__global__ void k_E(float* __restrict__ outE) {
    int bid = blockIdx.x;               // b*NPIX + n
    int n = bid % NPIX;
    int b = bid / NPIX;
    int x = n % WW, y = n / WW;
    int x0 = x >> 1, y0 = y >> 1;
    int x1 = min(x0 + 1, KW - 1), y1 = min(y0 + 1, KH - 1);
    float wx = (x & 1) ? 0.5f : 0.f;
    float wy = (y & 1) ? 0.5f : 0.f;
    float w00 = (1.f - wx) * (1.f - wy), w01 = wx * (1.f - wy);
    float w10 = (1.f - wx) * wy,         w11 = wx * wy;
    const float* g = d_gemb + (size_t)b * KK * DD;
    int d = threadIdx.x;
    float e = w00 * g[(y0 * KW + x0) * DD + d] + w01 * g[(y0 * KW + x1) * DD + d]
            + w10 * g[(y1 * KW + x0) * DD + d] + w11 * g[(y1 * KW + x1) * DD + d];
    float sq = e * e;
#pragma unroll
    for (int o = 16; o; o >>= 1) sq += __shfl_down_sync(0xffffffffu, sq, o);
    __shared__ float r4[4];
    __shared__ float nrm;
    int lane = d & 31, wid = d >> 5;
    if (lane == 0) r4[wid] = sq;
    __syncthreads();
    if (d == 0) nrm = sqrtf(r4[0] + r4[1] + r4[2] + r4[3]);
    __syncthreads();
    outE[(size_t)bid * DD + d] = e * (1.f / fmaxf(nrm, 1e-6f));
}

// ---------------- K5a: Saff = (E E^T) .* G  (exact R7/R12 kernel) ---------
#define LDA 132
__global__ void __launch_bounds__(256) k_saff(const float* __restrict__ E) {
    __shared__ __align__(16) float smem[4 * 16 * LDA];
    float* Ts = smem;
    int b = blockIdx.y;
    int bt = blockIdx.x;
    int bi = 0, rem = bt;
    while (rem >= NB - bi) { rem -= NB - bi; bi++; }
    int bj = bi + rem;
    int n0 = bi * TS, m0 = bj * TS;
    const float* Eb = E + (size_t)b * NPIX * DD;
    float* Sb = d_Saff + (size_t)b * NPIX * NPIX;

    int t = threadIdx.x;
    int ty = t >> 4, tx = t & 15;
    int lr = t >> 2;
    int lc = (t & 3) * 4;

    const float* gA0 = Eb + (size_t)min(n0 + lr,      NPIX - 1) * DD + lc;
    const float* gA1 = Eb + (size_t)min(n0 + lr + 64, NPIX - 1) * DD + lc;
    const float* gB0 = Eb + (size_t)min(m0 + lr,      NPIX - 1) * DD + lc;
    const float* gB1 = Eb + (size_t)min(m0 + lr + 64, NPIX - 1) * DD + lc;

    unsigned long long acc2[8][4];
#pragma unroll
    for (int i = 0; i < 8; i++)
#pragma unroll
        for (int q = 0; q < 4; q++) acc2[i][q] = 0ull;

    float4 pa0 = *(const float4*)gA0;
    float4 pa1 = *(const float4*)gA1;
    float4 pb0 = *(const float4*)gB0;
    float4 pb1 = *(const float4*)gB1;

    float* A0 = smem;
    float* B0 = smem + 16 * LDA;
    float* A1 = smem + 32 * LDA;
    float* B1 = smem + 48 * LDA;

    {
        float av0[4] = {pa0.x, pa0.y, pa0.z, pa0.w};
        float av1[4] = {pa1.x, pa1.y, pa1.z, pa1.w};
        float bv0[4] = {pb0.x, pb0.y, pb0.z, pb0.w};
        float bv1[4] = {pb1.x, pb1.y, pb1.z, pb1.w};
#pragma unroll
        for (int q = 0; q < 4; q++) {
            A0[(lc + q) * LDA + lr]      = av0[q];
            A0[(lc + q) * LDA + lr + 64] = av1[q];
            B0[(lc + q) * LDA + lr]      = bv0[q];
            B0[(lc + q) * LDA + lr + 64] = bv1[q];
        }
    }
    __syncthreads();

#pragma unroll 1
    for (int c = 0; c < 8; c++) {
        float* As = (c & 1) ? A1 : A0;
        float* Bs = (c & 1) ? B1 : B0;
        if (c < 7) {
            int off = (c + 1) * 16;
            pa0 = *(const float4*)(gA0 + off);
            pa1 = *(const float4*)(gA1 + off);
            pb0 = *(const float4*)(gB0 + off);
            pb1 = *(const float4*)(gB1 + off);
        }
#pragma unroll
        for (int kk = 0; kk < 16; kk++) {
            const float* Ak = As + kk * LDA;
            const float* Bk = Bs + kk * LDA;
            float a[8], bb[8];
            *(float4*)(a)      = *(const float4*)(Ak + ty * 4);
            *(float4*)(a + 4)  = *(const float4*)(Ak + 64 + ty * 4);
            *(float4*)(bb)     = *(const float4*)(Bk + tx * 4);
            *(float4*)(bb + 4) = *(const float4*)(Bk + 64 + tx * 4);
            unsigned long long bp[4];
#pragma unroll
            for (int q = 0; q < 4; q++) bp[q] = pk2(bb[2 * q], bb[2 * q + 1]);
#pragma unroll
            for (int i = 0; i < 8; i++) {
                unsigned long long ad = pk2(a[i], a[i]);
#pragma unroll
                for (int q = 0; q < 4; q++) ffma2(acc2[i][q], ad, bp[q]);
            }
        }
        if (c < 7) {
            float* An = (c & 1) ? A0 : A1;
            float* Bn = (c & 1) ? B0 : B1;
            float av0[4] = {pa0.x, pa0.y, pa0.z, pa0.w};
            float av1[4] = {pa1.x, pa1.y, pa1.z, pa1.w};
            float bv0[4] = {pb0.x, pb0.y, pb0.z, pb0.w};
            float bv1[4] = {pb1.x, pb1.y, pb1.z, pb1.w};
#pragma unroll
            for (int q = 0; q < 4; q++) {
                An[(lc + q) * LDA + lr]      = av0[q];
                An[(lc + q) * LDA + lr + 64] = av1[q];
                Bn[(lc + q) * LDA + lr]      = bv0[q];
                Bn[(lc + q) * LDA + lr + 64] = bv1[q];
            }
            __syncthreads();
        }
    }

    float acc[8][8];
#pragma unroll
    for (int i = 0; i < 8; i++)
#pragma unroll
        for (int q = 0; q < 4; q++) upk2(acc2[i][q], acc[i][2 * q], acc[i][2 * q + 1]);

#pragma unroll
    for (int i = 0; i < 8; i++) {
        int n = n0 + ((i < 4) ? (ty * 4 + i) : (64 + ty * 4 + i - 4));
        if (n >= NPIX) continue;
        int nx = n % WW, ny = n / WW;
#pragma unroll
        for (int h = 0; h < 2; h++) {
            int mb = m0 + h * 64 + tx * 4;
            if (mb >= NPIX) continue;
            float4 o;
            float ov[4];
#pragma unroll
            for (int j = 0; j < 4; j++) {
                int m = mb + j;
                int dx = nx - m % WW;
                int dy = ny - m / WW;
                ov[j] = acc[i][h * 4 + j] * __ldg(&d_Gtab[dx * dx + dy * dy]);
            }
            o.x = ov[0]; o.y = ov[1]; o.z = ov[2]; o.w = ov[3];
            *(float4*)(Sb + (size_t)n * NPIX + mb) = o;
        }
    }

    if (bi != bj) {
#pragma unroll 1
        for (int p = 0; p < 4; p++) {
            __syncthreads();
            int jh = p >> 1;
            int txlo = (p & 1) * 8;
            if (tx >= txlo && tx < txlo + 8) {
#pragma unroll
                for (int i = 0; i < 8; i++) {
                    int nl = (i < 4) ? (ty * 4 + i) : (64 + ty * 4 + i - 4);
#pragma unroll
                    for (int j = 0; j < 4; j++) {
                        int mrow = (tx - txlo) * 4 + j;
                        Ts[mrow * LDA + nl] = acc[i][jh * 4 + j];
                    }
                }
            }
            __syncthreads();
#pragma unroll
            for (int q = 0; q < 4; q++) {
                int fi = t + q * 256;
                int rown = fi >> 5;
                int c4 = (fi & 31) * 4;
                int m = m0 + 32 * p + rown;
                if (m >= NPIX) continue;
                int mx = m % WW, my = m / WW;
                float4 v = *(const float4*)(Ts + rown * LDA + c4);
                int nbase = n0 + c4;
                float vv[4] = {v.x, v.y, v.z, v.w};
                float4 o;
                float ov[4];
#pragma unroll
                for (int j = 0; j < 4; j++) {
                    int n = nbase + j;
                    int dx = mx - n % WW;
                    int dy = my - n / WW;
                    ov[j] = vv[j] * __ldg(&d_Gtab[dx * dx + dy * dy]);
                }
                o.x = ov[0]; o.y = ov[1]; o.z = ov[2]; o.w = ov[3];
                *(float4*)(Sb + (size_t)m * NPIX + nbase) = o;
            }
        }
    }
}

// ---------------- K5b: per-row top-32 via 4-level radix select -----------
// Bulk Saff reads use __ldcs (read-once, evict-first) — same values,
// better L2 policy while saff writebacks are still draining.
__global__ void __launch_bounds__(256) k_topk() {
    int row = blockIdx.x;           // b*NPIX + n
    int b = row / NPIX;
    int t = threadIdx.x;
    const float4* src4 = (const float4*)(d_Saff + (size_t)row * NPIX);
    __shared__ unsigned int hist[256];
    __shared__ unsigned int sufx[256];
    __shared__ unsigned int s_prefix;
    __shared__ int s_need, s_bin, s_cnt, s_last;
    __shared__ int   seli[TOPK];
    __shared__ float selv[TOPK];
    __shared__ int   redi[8];

    unsigned key[16];
    int nslot = (t < 16) ? 4 : 3;
#pragma unroll
    for (int q = 0; q < 4; q++) {
        if (q < nslot) {
            float4 v = __ldcs(&src4[t + q * 256]);
            float vv[4] = {v.x, v.y, v.z, v.w};
#pragma unroll
            for (int j = 0; j < 4; j++) {
                unsigned u = __float_as_uint(vv[j]);
                key[q * 4 + j] = (u & 0x80000000u) ? ~u : (u | 0x80000000u);
            }
        } else {
#pragma unroll
            for (int j = 0; j < 4; j++) key[q * 4 + j] = 0u;
        }
    }
    if (t == 0) { s_prefix = 0u; s_need = TOPK; s_cnt = 0; s_last = -1; }

#pragma unroll 1
    for (int level = 0; level < 4; level++) {
        int shift = 24 - level * 8;
        hist[t] = 0;
        __syncthreads();
        unsigned pref = s_prefix;
        int need0 = s_need;
#pragma unroll
        for (int s = 0; s < 16; s++) {
            if ((s >> 2) < nslot) {
                unsigned u = key[s];
                if (level == 0 || (u >> (shift + 8)) == (pref >> (shift + 8)))
                    atomicAdd(&hist[(u >> shift) & 0xFFu], 1u);
            }
        }
        __syncthreads();
        if (t < 32) {
            unsigned v[8], s = 0;
#pragma unroll
            for (int q = 7; q >= 0; q--) { s += hist[t * 8 + q]; v[q] = s; }
            unsigned x = s;
#pragma unroll
            for (int off = 1; off < 32; off <<= 1) {
                unsigned y = __shfl_down_sync(0xffffffffu, x, off);
                if (t + off < 32) x += y;
            }
            unsigned ex = x - s;
#pragma unroll
            for (int q = 0; q < 8; q++) sufx[t * 8 + q] = v[q] + ex;
        }
        __syncthreads();
        {
            unsigned ge = sufx[t];
            unsigned gn = (t == 255) ? 0u : sufx[t + 1];
            if (ge >= (unsigned)need0 && gn < (unsigned)need0) s_bin = t;
        }
        __syncthreads();
        if (t == 0) {
            int bsel = s_bin;
            if (bsel < 255) s_need -= (int)sufx[bsel + 1];
            s_prefix |= ((unsigned)bsel << shift);
        }
        __syncthreads();
    }

    unsigned T = s_prefix;
    int needEq = s_need;

#pragma unroll
    for (int s = 0; s < 16; s++) {
        if ((s >> 2) < nslot && key[s] > T) {
            int p = atomicAdd(&s_cnt, 1);
            seli[p] = (t + (s >> 2) * 256) * 4 + (s & 3);
        }
    }
    __syncthreads();
    int lane = t & 31, wid = t >> 5;
#pragma unroll 1
    for (int r = 0; r < needEq; r++) {
        int last = s_last;
        int li = NPIX;
#pragma unroll
        for (int s = 0; s < 16; s++) {
            if ((s >> 2) < nslot && key[s] == T) {
                int i = (t + (s >> 2) * 256) * 4 + (s & 3);
                if (i > last && i < li) li = i;
            }
        }
#pragma unroll
        for (int o = 16; o; o >>= 1) li = min(li, __shfl_down_sync(0xffffffffu, li, o));
        if (lane == 0) redi[wid] = li;
        __syncthreads();
        if (t == 0) {
            int m = redi[0];
#pragma unroll
            for (int w = 1; w < 8; w++) m = min(m, redi[w]);
            seli[s_cnt] = m;
            s_cnt++;
            s_last = m;
        }
        __syncthreads();
    }

    if (t < TOPK) {
        int m = seli[t];
        float v = d_Saff[(size_t)row * NPIX + m];
        selv[t] = v;
        d_topv[row * TOPK + t] = v;
        d_topi[row * TOPK + t] = m;
        atomicAdd(&d_cols[b * NPIX + m], expf(10.f * v) - 1.f);
    }
    __syncthreads();
    if (t == 0) {
        float rs = (float)(NPIX - TOPK);
        for (int j = 0; j < TOPK; j++) rs += expf(10.f * selv[j]);
        d_irow[row] = 1.f / rs;
    }
}

// ---------------- K5c: invert colsums -----------------------------------
__global__ void k_invcol() {
    int i = blockIdx.x * blockDim.x + threadIdx.x;
    if (i < BB * NPIX) d_cols[i] = 1.f / d_cols[i];
}

// ------- K5d: A0 = rank-1 background + top-k scatter overrides -----------
// Background stores use __stcs (never re-read on device) — bit-identical.
__global__ void __launch_bounds__(256) k_a0(float* __restrict__ outA) {
    int row = blockIdx.x;           // b*NPIX + n
    int b = row / NPIX;
    int t = threadIdx.x;
    float rn = d_irow[row];
    float4* out4 = (float4*)(outA + (size_t)row * NPIX);
    const float4* ic4 = (const float4*)(d_cols + b * NPIX);
    for (int f = t; f < NPIX / 4; f += 256) {
        float4 c = ic4[f];
        float4 o;
        o.x = rn * c.x; o.y = rn * c.y; o.z = rn * c.z; o.w = rn * c.w;
        __stcs(&out4[f], o);
    }
    __syncthreads();
    if (t < TOPK) {
        int m = d_topi[row * TOPK + t];
        float v = d_topv[row * TOPK + t];
        float e = expf(10.f * v);
        outA[(size_t)row * NPIX + m] = e * e * rn * (d_cols + b * NPIX)[m];
    }
}

// -------------------------------------------------------------------------
extern "C" void kernel_launch(void* const* d_in, const int* in_sizes, int n_in,
                              void* d_out, int out_size) {
    const float* fm  = (const float*)d_in[0];
    const float* A   = (const float*)d_in[1];
    const float* pww = (const float*)d_in[2];
    const float* pwb = (const float*)d_in[3];
    const float* prw = (const float*)d_in[4];
    const float* prb = (const float*)d_in[5];
    const float* r   = (const float*)d_in[6];

    float* outE = (float*)d_out;                        // (B, N, D)
    float* outA = outE + (size_t)BB * NPIX * DD;        // (B, N, N)

    cudaFuncSetAttribute(k_zproj, cudaFuncAttributeMaxDynamicSharedMemorySize,
                         ZP_SMEM);

    k_init<<<49, 256>>>();
    k_fmp<<<dim3(NPIX / 32, BB), 256>>>(fm, pww);
    k_warppool<<<TT * BB * HH, 256>>>(A);
    k_zproj<<<TT * BB * (KH / 2), 128, ZP_SMEM>>>(pwb, prw, prb);
    k_gemb<<<BB * KK, 128>>>(r);
    k_E<<<BB * NPIX, 128>>>(outE);
    k_saff<<<dim3(NTRI, BB), 256>>>(outE);
    k_topk<<<BB * NPIX, 256>>>();
    k_invcol<<<49, 256>>>();
    k_a0<<<BB * NPIX, 256>>>(outA);
}

// round 17
// speedup vs baseline: 1.1940x; 1.0452x over previous
#include <cuda_runtime.h>
#include <math.h>

#define BB 4
#define CC 256
#define HH 56
#define WW 56
#define NPIX 3136
#define TT 16
#define MCH 64
#define DD 128
#define KH 28
#define KW 28
#define KK 784
#define TOPK 32
#define GTAB_N 6051
#define TS 128
#define NB 25      /* ceil(3136/128) */
#define NTRI 325   /* 25*26/2 */

// ---------------- scratch (device globals; no allocation) ----------------
__device__ float d_fmp[BB * NPIX * MCH];              // [b][n][m]
__device__ float d_rp[TT * BB * HH * KW * MCH];       // [t][b][y][kx][m]
__device__ float d_Z[BB * TT * KK * DD];              // [b][t][k][d]
__device__ float d_gemb[BB * KK * DD];                // [b][k][d]
__device__ __align__(128) float d_Saff[(size_t)BB * NPIX * NPIX];
__device__ float d_topv[BB * NPIX * TOPK];
__device__ int   d_topi[BB * NPIX * TOPK];
__device__ float d_irow[BB * NPIX];
__device__ float d_cols[BB * NPIX];                   // colsum, then inverted
__device__ float d_Gtab[GTAB_N];

// ---------------- f32x2 packed helpers (bit-exact dual IEEE-RN FMA) ------
__device__ __forceinline__ unsigned long long pk2(float lo, float hi) {
    unsigned long long r;
    asm("mov.b64 %0, {%1, %2};" : "=l"(r) : "f"(lo), "f"(hi));
    return r;
}
__device__ __forceinline__ void upk2(unsigned long long v, float &lo, float &hi) {
    asm("mov.b64 {%0, %1}, %2;" : "=f"(lo), "=f"(hi) : "l"(v));
}
__device__ __forceinline__ void ffma2(unsigned long long &d,
                                      unsigned long long a, unsigned long long b) {
    asm("fma.rn.f32x2 %0, %1, %2, %0;" : "+l"(d) : "l"(a), "l"(b));
}

// ---------------- init: G table + colsum reset (every replay) ------------
__global__ void k_init() {
    int i = blockIdx.x * blockDim.x + threadIdx.x;
    if (i < GTAB_N) d_Gtab[i] = 1.f - expf(-(float)i / 18.f);
    if (i < BB * NPIX) d_cols[i] = (float)NPIX;
}

// ---------------- K1: fmp[b][n][m] = sum_c fm[b][c][n] * pw_w[m][c] ------
__global__ void k_fmp(const float* __restrict__ fm, const float* __restrict__ pw) {
    __shared__ float sF[32][32];
    __shared__ float sW[32][64];
    int b = blockIdx.y;
    int n0 = blockIdx.x * 32;
    int t = threadIdx.x;
    int nl = t & 31;
    int m0 = (t >> 5) * 8;
    float acc[8];
#pragma unroll
    for (int j = 0; j < 8; j++) acc[j] = 0.f;
    for (int c0 = 0; c0 < CC; c0 += 32) {
        __syncthreads();
#pragma unroll
        for (int q = 0; q < 4; q++) {
            int l = t + q * 256; int c = l >> 5; int n = l & 31;
            sF[c][n] = fm[(b * CC + c0 + c) * NPIX + n0 + n];
        }
#pragma unroll
        for (int q = 0; q < 8; q++) {
            int l = t + q * 256; int c = l >> 6; int m = l & 63;
            sW[c][m] = pw[m * CC + c0 + c];
        }
        __syncthreads();
#pragma unroll
        for (int c = 0; c < 32; c++) {
            float a = sF[c][nl];
#pragma unroll
            for (int j = 0; j < 8; j++) acc[j] += a * sW[c][m0 + j];
        }
    }
#pragma unroll
    for (int j = 0; j < 8; j++)
        d_fmp[(size_t)(b * NPIX + n0 + nl) * MCH + m0 + j] = acc[j];
}

// --- K2: fused affine-warp bilinear sample + 9-wide row pooling ----------
__global__ void __launch_bounds__(256) k_warppool(const float* __restrict__ A) {
    __shared__ float2 sw[WW * 32];        // 56 x 32 float2 = 14336 B
    int bid = blockIdx.x;                 // tb*HH + y
    int y = bid % HH;
    int tb = bid / HH;                    // tt*4 + b
    int b = tb & 3;
    int tt = tb >> 2;
    int t = threadIdx.x;
    int w = t >> 5, lane = t & 31;
    const float* Ar = A + tt * 6;
    float gy = (2.f * (float)y + 1.f) / (float)HH - 1.f;
    const float2* p = (const float2*)(d_fmp + (size_t)b * NPIX * MCH);

    for (int x = w; x < WW; x += 8) {
        float gx = (2.f * (float)x + 1.f) / (float)WW - 1.f;
        float grx = gx * Ar[0] + gy * Ar[1] + Ar[2];
        float gry = gx * Ar[3] + gy * Ar[4] + Ar[5];
        float ix = ((grx + 1.f) * (float)WW - 1.f) * 0.5f;
        float iy = ((gry + 1.f) * (float)HH - 1.f) * 0.5f;
        float x0f = floorf(ix), y0f = floorf(iy);
        float wx = ix - x0f, wy = iy - y0f;
        int x0 = (int)x0f, y0 = (int)y0f;
        int x0c = min(max(x0, 0), WW - 1), x1c = min(max(x0 + 1, 0), WW - 1);
        int y0c = min(max(y0, 0), HH - 1), y1c = min(max(y0 + 1, 0), HH - 1);
        float2 v00 = p[(y0c * WW + x0c) * 32 + lane];
        float2 v01 = p[(y0c * WW + x1c) * 32 + lane];
        float2 v10 = p[(y1c * WW + x0c) * 32 + lane];
        float2 v11 = p[(y1c * WW + x1c) * 32 + lane];
        float w00 = (1.f - wx) * (1.f - wy), w01 = wx * (1.f - wy);
        float w10 = (1.f - wx) * wy,         w11 = wx * wy;
        float2 o;
        o.x = v00.x * w00 + v01.x * w01 + v10.x * w10 + v11.x * w11;
        o.y = v00.y * w00 + v01.y * w01 + v10.y * w10 + v11.y * w11;
        sw[x * 32 + lane] = o;
    }
    __syncthreads();

    for (int kx = w; kx < KW; kx += 8) {
        float2 acc = make_float2(0.f, 0.f);
        int xs0 = 2 * kx - 4;
#pragma unroll
        for (int d = 0; d < 9; d++) {
            int xx = xs0 + d;
            if (xx >= 0 && xx < WW) {
                float2 v = sw[xx * 32 + lane];
                acc.x += v.x; acc.y += v.y;
            }
        }
        ((float2*)d_rp)[((size_t)(tb * HH + y) * KW + kx) * 32 + lane] = acc;
    }
}

// ------- K2c: col pool + /81 + pw_b + proj (64->128) + L2 normalize ------
// Two units of 64 threads per block (one ky each); each thread computes TWO
// d-columns (d, d+64). All accumulation chains / rounding identical to the
// validated path -> bit-exact Z.
#define ZP_SMEM ((DD * 65 + 2 * MCH * 36 + 2 * 4 * KW) * 4)
__global__ void __launch_bounds__(128) k_zproj(const float* __restrict__ pwb,
                                               const float* __restrict__ prw,
                                               const float* __restrict__ prb) {
    extern __shared__ float zsm[];
    float* w_s  = zsm;                         // [d][m] pad 65
    float* xs_a = zsm + DD * 65;               // 2 units x [m][kx] pad 36
    float* reda = xs_a + 2 * MCH * 36;         // 2 units x 4*KW
    int bid = blockIdx.x;                      // tb*14 + kyp
    int kyp = bid % (KH / 2);
    int tb = bid / (KH / 2);                   // tt*4 + b
    int b = tb & 3, tt = tb >> 2;
    int t = threadIdx.x;
    int u = t >> 6;                            // unit 0/1
    int ut = t & 63;                           // d0 = ut, d1 = ut+64
    int ky = 2 * kyp + u;
    float* xs_u = xs_a + u * (MCH * 36);
    float* red_u = reda + u * (4 * KW);

    {
        const float4* p4 = (const float4*)prw;    // 2048 float4
#pragma unroll
        for (int i = 0; i < 16; i++) {
            int idx4 = t + i * 128;
            float4 v = p4[idx4];
            int idx = idx4 * 4;
            int d = idx >> 6, m = idx & 63;
            float* w = &w_s[d * 65 + m];
            w[0] = v.x; w[1] = v.y; w[2] = v.z; w[3] = v.w;
        }
    }

    {
        float a[28];
#pragma unroll
        for (int i = 0; i < 28; i++) a[i] = 0.f;
        int ys0 = 2 * ky - 4;
        const float* rbase = d_rp + (size_t)tb * HH * KW * MCH;
        for (int dyy = 0; dyy < 9; dyy++) {
            int yy = ys0 + dyy;
            if (yy < 0 || yy >= HH) continue;
            const float* rrow = rbase + (size_t)yy * (KW * MCH);
#pragma unroll
            for (int i = 0; i < 28; i++) a[i] += rrow[ut + i * 64];
        }
        float pwbm = pwb[ut];
#pragma unroll
        for (int i = 0; i < 28; i++)
            xs_u[ut * 36 + i] = a[i] / 81.f + pwbm;     // exact R3 rounding
    }
    __syncthreads();

    float acc0[28], acc1[28];
    float pb0 = prb[ut], pb1 = prb[ut + 64];
#pragma unroll
    for (int p = 0; p < 28; p++) { acc0[p] = pb0; acc1[p] = pb1; }
    const float* wr0 = w_s + ut * 65;
    const float* wr1 = w_s + (ut + 64) * 65;
    for (int m = 0; m < MCH; m++) {
        float w0 = wr0[m];
        float w1 = wr1[m];
        const float4* xr = (const float4*)(xs_u + m * 36);
#pragma unroll
        for (int q = 0; q < 7; q++) {
            float4 x4 = xr[q];
            acc0[4 * q]     += x4.x * w0;  acc1[4 * q]     += x4.x * w1;
            acc0[4 * q + 1] += x4.y * w0;  acc1[4 * q + 1] += x4.y * w1;
            acc0[4 * q + 2] += x4.z * w0;  acc1[4 * q + 2] += x4.z * w1;
            acc0[4 * q + 3] += x4.w * w0;  acc1[4 * q + 3] += x4.w * w1;
        }
    }

    int lane = t & 31;
    int wu = (t >> 5) & 1;                 // warp within unit
#pragma unroll
    for (int p = 0; p < 28; p++) {
        float sq0 = acc0[p] * acc0[p];
        float sq1 = acc1[p] * acc1[p];
#pragma unroll
        for (int o = 16; o; o >>= 1) {
            sq0 += __shfl_down_sync(0xffffffffu, sq0, o);
            sq1 += __shfl_down_sync(0xffffffffu, sq1, o);
        }
        if (lane == 0) {
            red_u[wu * 28 + p]       = sq0;
            red_u[(2 + wu) * 28 + p] = sq1;
        }
    }
    __syncthreads();
    size_t zbase = (((size_t)b * TT + tt) * KK + (size_t)ky * KW) * DD;
#pragma unroll
    for (int p = 0; p < 28; p++) {
        float nrm = sqrtf(red_u[p] + red_u[28 + p] + red_u[56 + p] + red_u[84 + p]);
        float inv = 1.f / fmaxf(nrm, 1e-6f);            // exact R3 rounding
        d_Z[zbase + (size_t)p * DD + ut]      = acc0[p] * inv;
        d_Z[zbase + (size_t)p * DD + ut + 64] = acc1[p] * inv;
    }
}

// ---------------- K3: softmax over T, g_emb[b][k][d] ---------------------
__global__ void k_gemb(const float* __restrict__ r) {
    int bid = blockIdx.x;
    int b = bid / KK, k = bid % KK;
    int d = threadIdx.x;
    float v[TT];
#pragma unroll
    for (int t = 0; t < TT; t++)
        v[t] = d_Z[(((size_t)b * TT + t) * KK + k) * DD + d];
    float rv = r[d];
    __shared__ float part[4][TT];
    __shared__ float sv[TT];
    int lane = d & 31, wid = d >> 5;
#pragma unroll
    for (int t = 0; t < TT; t++) {
        float p = v[t] * rv;
#pragma unroll
        for (int o = 16; o; o >>= 1) p += __shfl_down_sync(0xffffffffu, p, o);
        if (lane == 0) part[wid][t] = p;
    }
    __syncthreads();
    if (d < TT) sv[d] = part[0][d] + part[1][d] + part[2][d] + part[3][d];
    __syncthreads();
    float mx = -1e30f;
#pragma unroll
    for (int t = 0; t < TT; t++) mx = fmaxf(mx, 10.f * sv[t]);
    float den = 0.f, g = 0.f;
#pragma unroll
    for (int t = 0; t < TT; t++) {
        float wgt = expf(10.f * sv[t] - mx);
        den += wgt;
        g += wgt * v[t];
    }
    d_gemb[((size_t)b * KK + k) * DD + d] = g / den;
}

// ---------------- K4: E = bilinear(g_emb), L2 normalize, -> d_out --------
__global__ void k_E(float* __restrict__ outE) {
    int bid = blockIdx.x;               // b*NPIX + n
    int n = bid % NPIX;
    int b = bid / NPIX;
    int x = n % WW, y = n / WW;
    int x0 = x >> 1, y0 = y >> 1;
    int x1 = min(x0 + 1, KW - 1), y1 = min(y0 + 1, KH - 1);
    float wx = (x & 1) ? 0.5f : 0.f;
    float wy = (y & 1) ? 0.5f : 0.f;
    float w00 = (1.f - wx) * (1.f - wy), w01 = wx * (1.f - wy);
    float w10 = (1.f - wx) * wy,         w11 = wx * wy;
    const float* g = d_gemb + (size_t)b * KK * DD;
    int d = threadIdx.x;
    float e = w00 * g[(y0 * KW + x0) * DD + d] + w01 * g[(y0 * KW + x1) * DD + d]
            + w10 * g[(y1 * KW + x0) * DD + d] + w11 * g[(y1 * KW + x1) * DD + d];
    float sq = e * e;
#pragma unroll
    for (int o = 16; o; o >>= 1) sq += __shfl_down_sync(0xffffffffu, sq, o);
    __shared__ float r4[4];
    __shared__ float nrm;
    int lane = d & 31, wid = d >> 5;
    if (lane == 0) r4[wid] = sq;
    __syncthreads();
    if (d == 0) nrm = sqrtf(r4[0] + r4[1] + r4[2] + r4[3]);
    __syncthreads();
    outE[(size_t)bid * DD + d] = e * (1.f / fmaxf(nrm, 1e-6f));
}

// ---------------- K5a: Saff = (E E^T) .* G  -------------------------------
// Mainloop identical to the validated R12 kernel. Mirror epilogue: post-G
// values staged into a 128x132 smem buffer during the normal write (G is
// symmetric, so mirror values are the SAME fp32 products) -> one barrier +
// one coalesced copy instead of 4 phases / 8 barriers / duplicate G math.
#define LDA 132
#define SAFF_SMEM (DD * LDA * 4)   /* 67584 B; mainloop's 4*16*LDA aliases it */
__global__ void __launch_bounds__(256) k_saff(const float* __restrict__ E) {
    extern __shared__ __align__(16) float smem[];
    float* Ts = smem;                  // transpose buffer [m_local][n_local]
    int b = blockIdx.y;
    int bt = blockIdx.x;
    int bi = 0, rem = bt;
    while (rem >= NB - bi) { rem -= NB - bi; bi++; }
    int bj = bi + rem;
    int n0 = bi * TS, m0 = bj * TS;
    const float* Eb = E + (size_t)b * NPIX * DD;
    float* Sb = d_Saff + (size_t)b * NPIX * NPIX;

    int t = threadIdx.x;
    int ty = t >> 4, tx = t & 15;
    int lr = t >> 2;
    int lc = (t & 3) * 4;

    const float* gA0 = Eb + (size_t)min(n0 + lr,      NPIX - 1) * DD + lc;
    const float* gA1 = Eb + (size_t)min(n0 + lr + 64, NPIX - 1) * DD + lc;
    const float* gB0 = Eb + (size_t)min(m0 + lr,      NPIX - 1) * DD + lc;
    const float* gB1 = Eb + (size_t)min(m0 + lr + 64, NPIX - 1) * DD + lc;

    unsigned long long acc2[8][4];
#pragma unroll
    for (int i = 0; i < 8; i++)
#pragma unroll
        for (int q = 0; q < 4; q++) acc2[i][q] = 0ull;

    float4 pa0 = *(const float4*)gA0;
    float4 pa1 = *(const float4*)gA1;
    float4 pb0 = *(const float4*)gB0;
    float4 pb1 = *(const float4*)gB1;

    float* A0 = smem;
    float* B0 = smem + 16 * LDA;
    float* A1 = smem + 32 * LDA;
    float* B1 = smem + 48 * LDA;

    {
        float av0[4] = {pa0.x, pa0.y, pa0.z, pa0.w};
        float av1[4] = {pa1.x, pa1.y, pa1.z, pa1.w};
        float bv0[4] = {pb0.x, pb0.y, pb0.z, pb0.w};
        float bv1[4] = {pb1.x, pb1.y, pb1.z, pb1.w};
#pragma unroll
        for (int q = 0; q < 4; q++) {
            A0[(lc + q) * LDA + lr]      = av0[q];
            A0[(lc + q) * LDA + lr + 64] = av1[q];
            B0[(lc + q) * LDA + lr]      = bv0[q];
            B0[(lc + q) * LDA + lr + 64] = bv1[q];
        }
    }
    __syncthreads();

#pragma unroll 1
    for (int c = 0; c < 8; c++) {
        float* As = (c & 1) ? A1 : A0;
        float* Bs = (c & 1) ? B1 : B0;
        if (c < 7) {
            int off = (c + 1) * 16;
            pa0 = *(const float4*)(gA0 + off);
            pa1 = *(const float4*)(gA1 + off);
            pb0 = *(const float4*)(gB0 + off);
            pb1 = *(const float4*)(gB1 + off);
        }
#pragma unroll
        for (int kk = 0; kk < 16; kk++) {
            const float* Ak = As + kk * LDA;
            const float* Bk = Bs + kk * LDA;
            float a[8], bb[8];
            *(float4*)(a)      = *(const float4*)(Ak + ty * 4);
            *(float4*)(a + 4)  = *(const float4*)(Ak + 64 + ty * 4);
            *(float4*)(bb)     = *(const float4*)(Bk + tx * 4);
            *(float4*)(bb + 4) = *(const float4*)(Bk + 64 + tx * 4);
            unsigned long long bp[4];
#pragma unroll
            for (int q = 0; q < 4; q++) bp[q] = pk2(bb[2 * q], bb[2 * q + 1]);
#pragma unroll
            for (int i = 0; i < 8; i++) {
                unsigned long long ad = pk2(a[i], a[i]);
#pragma unroll
                for (int q = 0; q < 4; q++) ffma2(acc2[i][q], ad, bp[q]);
            }
        }
        if (c < 7) {
            float* An = (c & 1) ? A0 : A1;
            float* Bn = (c & 1) ? B0 : B1;
            float av0[4] = {pa0.x, pa0.y, pa0.z, pa0.w};
            float av1[4] = {pa1.x, pa1.y, pa1.z, pa1.w};
            float bv0[4] = {pb0.x, pb0.y, pb0.z, pb0.w};
            float bv1[4] = {pb1.x, pb1.y, pb1.z, pb1.w};
#pragma unroll
            for (int q = 0; q < 4; q++) {
                An[(lc + q) * LDA + lr]      = av0[q];
                An[(lc + q) * LDA + lr + 64] = av1[q];
                Bn[(lc + q) * LDA + lr]      = bv0[q];
                Bn[(lc + q) * LDA + lr + 64] = bv1[q];
            }
            __syncthreads();
        }
    }

    float acc[8][8];
#pragma unroll
    for (int i = 0; i < 8; i++)
#pragma unroll
        for (int q = 0; q < 4; q++) upk2(acc2[i][q], acc[i][2 * q], acc[i][2 * q + 1]);

    bool mirror = (bi != bj);
    if (mirror) __syncthreads();      // mainloop smem reads done before Ts reuse

    // ---- normal tile write (coalesced, G applied) + Ts staging ----
#pragma unroll
    for (int i = 0; i < 8; i++) {
        int nl = (i < 4) ? (ty * 4 + i) : (64 + ty * 4 + i - 4);
        int n = n0 + nl;
        if (n >= NPIX) continue;
        int nx = n % WW, ny = n / WW;
#pragma unroll
        for (int h = 0; h < 2; h++) {
            int mb = m0 + h * 64 + tx * 4;
            if (mb >= NPIX) continue;
            float4 o;
            float ov[4];
#pragma unroll
            for (int j = 0; j < 4; j++) {
                int m = mb + j;
                int dx = nx - m % WW;
                int dy = ny - m / WW;
                ov[j] = acc[i][h * 4 + j] * __ldg(&d_Gtab[dx * dx + dy * dy]);
            }
            o.x = ov[0]; o.y = ov[1]; o.z = ov[2]; o.w = ov[3];
            *(float4*)(Sb + (size_t)n * NPIX + mb) = o;
            if (mirror) {
                int mloc = h * 64 + tx * 4;
#pragma unroll
                for (int j = 0; j < 4; j++)
                    Ts[(mloc + j) * LDA + nl] = ov[j];
            }
        }
    }

    // ---- mirror tile: single coalesced copy (G symmetric -> same values) ----
    if (mirror) {
        __syncthreads();
#pragma unroll
        for (int q = 0; q < 16; q++) {
            int fi = t + q * 256;
            int row = fi >> 5;            // 0..127
            int c4 = (fi & 31) * 4;       // 0..124
            int m = m0 + row;
            if (m < NPIX) {
                float4 v = *(const float4*)(Ts + row * LDA + c4);
                *(float4*)(Sb + (size_t)m * NPIX + n0 + c4) = v;
            }
        }
    }
}

// ---------------- K5b: per-row top-32 via 4-level radix select -----------
__global__ void __launch_bounds__(256) k_topk() {
    int row = blockIdx.x;           // b*NPIX + n
    int b = row / NPIX;
    int t = threadIdx.x;
    const float4* src4 = (const float4*)(d_Saff + (size_t)row * NPIX);
    __shared__ unsigned int hist[256];
    __shared__ unsigned int sufx[256];
    __shared__ unsigned int s_prefix;
    __shared__ int s_need, s_bin, s_cnt, s_last;
    __shared__ int   seli[TOPK];
    __shared__ float selv[TOPK];
    __shared__ int   redi[8];

    unsigned key[16];
    int nslot = (t < 16) ? 4 : 3;
#pragma unroll
    for (int q = 0; q < 4; q++) {
        if (q < nslot) {
            float4 v = src4[t + q * 256];
            float vv[4] = {v.x, v.y, v.z, v.w};
#pragma unroll
            for (int j = 0; j < 4; j++) {
                unsigned u = __float_as_uint(vv[j]);
                key[q * 4 + j] = (u & 0x80000000u) ? ~u : (u | 0x80000000u);
            }
        } else {
#pragma unroll
            for (int j = 0; j < 4; j++) key[q * 4 + j] = 0u;
        }
    }
    if (t == 0) { s_prefix = 0u; s_need = TOPK; s_cnt = 0; s_last = -1; }

#pragma unroll 1
    for (int level = 0; level < 4; level++) {
        int shift = 24 - level * 8;
        hist[t] = 0;
        __syncthreads();
        unsigned pref = s_prefix;
        int need0 = s_need;
#pragma unroll
        for (int s = 0; s < 16; s++) {
            if ((s >> 2) < nslot) {
                unsigned u = key[s];
                if (level == 0 || (u >> (shift + 8)) == (pref >> (shift + 8)))
                    atomicAdd(&hist[(u >> shift) & 0xFFu], 1u);
            }
        }
        __syncthreads();
        if (t < 32) {
            unsigned v[8], s = 0;
#pragma unroll
            for (int q = 7; q >= 0; q--) { s += hist[t * 8 + q]; v[q] = s; }
            unsigned x = s;
#pragma unroll
            for (int off = 1; off < 32; off <<= 1) {
                unsigned y = __shfl_down_sync(0xffffffffu, x, off);
                if (t + off < 32) x += y;
            }
            unsigned ex = x - s;
#pragma unroll
            for (int q = 0; q < 8; q++) sufx[t * 8 + q] = v[q] + ex;
        }
        __syncthreads();
        {
            unsigned ge = sufx[t];
            unsigned gn = (t == 255) ? 0u : sufx[t + 1];
            if (ge >= (unsigned)need0 && gn < (unsigned)need0) s_bin = t;
        }
        __syncthreads();
        if (t == 0) {
            int bsel = s_bin;
            if (bsel < 255) s_need -= (int)sufx[bsel + 1];
            s_prefix |= ((unsigned)bsel << shift);
        }
        __syncthreads();
    }

    unsigned T = s_prefix;
    int needEq = s_need;

#pragma unroll
    for (int s = 0; s < 16; s++) {
        if ((s >> 2) < nslot && key[s] > T) {
            int p = atomicAdd(&s_cnt, 1);
            seli[p] = (t + (s >> 2) * 256) * 4 + (s & 3);
        }
    }
    __syncthreads();
    int lane = t & 31, wid = t >> 5;
#pragma unroll 1
    for (int r = 0; r < needEq; r++) {
        int last = s_last;
        int li = NPIX;
#pragma unroll
        for (int s = 0; s < 16; s++) {
            if ((s >> 2) < nslot && key[s] == T) {
                int i = (t + (s >> 2) * 256) * 4 + (s & 3);
                if (i > last && i < li) li = i;
            }
        }
#pragma unroll
        for (int o = 16; o; o >>= 1) li = min(li, __shfl_down_sync(0xffffffffu, li, o));
        if (lane == 0) redi[wid] = li;
        __syncthreads();
        if (t == 0) {
            int m = redi[0];
#pragma unroll
            for (int w = 1; w < 8; w++) m = min(m, redi[w]);
            seli[s_cnt] = m;
            s_cnt++;
            s_last = m;
        }
        __syncthreads();
    }

    if (t < TOPK) {
        int m = seli[t];
        float v = d_Saff[(size_t)row * NPIX + m];
        selv[t] = v;
        d_topv[row * TOPK + t] = v;
        d_topi[row * TOPK + t] = m;
        atomicAdd(&d_cols[b * NPIX + m], expf(10.f * v) - 1.f);
    }
    __syncthreads();
    if (t == 0) {
        float rs = (float)(NPIX - TOPK);
        for (int j = 0; j < TOPK; j++) rs += expf(10.f * selv[j]);
        d_irow[row] = 1.f / rs;
    }
}

// ---------------- K5c: invert colsums -----------------------------------
__global__ void k_invcol() {
    int i = blockIdx.x * blockDim.x + threadIdx.x;
    if (i < BB * NPIX) d_cols[i] = 1.f / d_cols[i];
}

// ------- K5d: A0 = rank-1 background + top-k scatter overrides -----------
__global__ void __launch_bounds__(256) k_a0(float* __restrict__ outA) {
    int row = blockIdx.x;           // b*NPIX + n
    int b = row / NPIX;
    int t = threadIdx.x;
    float rn = d_irow[row];
    float4* out4 = (float4*)(outA + (size_t)row * NPIX);
    const float4* ic4 = (const float4*)(d_cols + b * NPIX);
    for (int f = t; f < NPIX / 4; f += 256) {
        float4 c = ic4[f];
        float4 o;
        o.x = rn * c.x; o.y = rn * c.y; o.z = rn * c.z; o.w = rn * c.w;
        out4[f] = o;
    }
    __syncthreads();
    if (t < TOPK) {
        int m = d_topi[row * TOPK + t];
        float v = d_topv[row * TOPK + t];
        float e = expf(10.f * v);
        outA[(size_t)row * NPIX + m] = e * e * rn * (d_cols + b * NPIX)[m];
    }
}

// -------------------------------------------------------------------------
extern "C" void kernel_launch(void* const* d_in, const int* in_sizes, int n_in,
                              void* d_out, int out_size) {
    const float* fm  = (const float*)d_in[0];
    const float* A   = (const float*)d_in[1];
    const float* pww = (const float*)d_in[2];
    const float* pwb = (const float*)d_in[3];
    const float* prw = (const float*)d_in[4];
    const float* prb = (const float*)d_in[5];
    const float* r   = (const float*)d_in[6];

    float* outE = (float*)d_out;                        // (B, N, D)
    float* outA = outE + (size_t)BB * NPIX * DD;        // (B, N, N)

    cudaFuncSetAttribute(k_zproj, cudaFuncAttributeMaxDynamicSharedMemorySize,
                         ZP_SMEM);
    cudaFuncSetAttribute(k_saff, cudaFuncAttributeMaxDynamicSharedMemorySize,
                         SAFF_SMEM);

    k_init<<<49, 256>>>();
    k_fmp<<<dim3(NPIX / 32, BB), 256>>>(fm, pww);
    k_warppool<<<TT * BB * HH, 256>>>(A);
    k_zproj<<<TT * BB * (KH / 2), 128, ZP_SMEM>>>(pwb, prw, prb);
    k_gemb<<<BB * KK, 128>>>(r);
    k_E<<<BB * NPIX, 128>>>(outE);
    k_saff<<<dim3(NTRI, BB), 256, SAFF_SMEM>>>(outE);
    k_topk<<<BB * NPIX, 256>>>();
    k_invcol<<<49, 256>>>();
    k_a0<<<BB * NPIX, 256>>>(outA);
}